// round 4
// baseline (speedup 1.0000x reference)
#include <cuda_runtime.h>
#include <cstdint>

#define N_IN    16
#define N_MF    2
#define N_RULES 64
#define NPAIR   32        // rule pairs processed per loop iteration
#define TPB     64
#define RPT     2         // rows per thread, packed into f32x2 lanes

typedef unsigned long long ull;

// ---------- f32x2 helpers (sm_100a packed fp32) ----------
__device__ __forceinline__ ull pack2(float lo, float hi) {
    ull r;
    asm("mov.b64 %0, {%1, %2};" : "=l"(r) : "f"(lo), "f"(hi));
    return r;
}
__device__ __forceinline__ void unpack2(ull v, float& lo, float& hi) {
    asm("mov.b64 {%0, %1}, %2;" : "=f"(lo), "=f"(hi) : "l"(v));
}
__device__ __forceinline__ ull ffma2(ull a, ull b, ull c) {
    ull d;
    asm("fma.rn.f32x2 %0, %1, %2, %3;" : "=l"(d) : "l"(a), "l"(b), "l"(c));
    return d;
}
__device__ __forceinline__ ull fadd2(ull a, ull b) {
    ull d;
    asm("add.rn.f32x2 %0, %1, %2;" : "=l"(d) : "l"(a), "l"(b));
    return d;
}
__device__ __forceinline__ ull fmul2(ull a, ull b) {
    ull d;
    asm("mul.rn.f32x2 %0, %1, %2;" : "=l"(d) : "l"(a), "l"(b));
    return d;
}
__device__ __forceinline__ float ex2_fast(float x) {
    float y;
    asm("ex2.approx.f32 %0, %1;" : "=f"(y) : "f"(x));
    return y;
}

// -0.5 * log2(e), 1/ln(2)
#define NEG_HALF_LOG2E (-0.7213475204444817f)
#define LOG2E          ( 1.4426950408889634f)

// ---------- constant blob: all warp-uniform operands, pre-duplicated ----------
struct Blob {
    float4 mask4[NPAIR][N_IN];      // (m_e, m_e, m_o, m_o)
    float4 cons4[NPAIR][N_IN + 1];  // (c_e, c_e, c_o, c_o); [16] = bias
    float4 am4[NPAIR];              // (a_e, a_e, a_o, a_o)
    float2 vfb2[N_IN + 1];          // fallback vector, duplicated (v, v)
    float2 cen[N_IN];               // (c0, c1)
    float2 inv[N_IN];               // 1/(exp(log_sigma)+1e-6)
};

__constant__ Blob c_blob;
__device__   Blob g_stage;

// ---------- prep kernel: build the blob in the staging buffer ----------
__global__ void prep_kernel(const float* __restrict__ center,
                            const float* __restrict__ log_sigma,
                            const float* __restrict__ consequent,
                            const int*   __restrict__ rule_idx,
                            const float* __restrict__ amask)
{
    const int tid = threadIdx.x;

    for (int idx = tid; idx < NPAIR * N_IN; idx += blockDim.x) {
        int p = idx >> 4, i = idx & 15;
        float m0 = (float)rule_idx[(2 * p)     * N_IN + i];
        float m1 = (float)rule_idx[(2 * p + 1) * N_IN + i];
        g_stage.mask4[p][i] = make_float4(m0, m0, m1, m1);
    }
    for (int idx = tid; idx < NPAIR * (N_IN + 1); idx += blockDim.x) {
        int p = idx / (N_IN + 1), i = idx % (N_IN + 1);
        float c0 = consequent[(2 * p)     * (N_IN + 1) + i];
        float c1 = consequent[(2 * p + 1) * (N_IN + 1) + i];
        g_stage.cons4[p][i] = make_float4(c0, c0, c1, c1);
    }
    if (tid < NPAIR) {
        float a0 = amask[2 * tid], a1 = amask[2 * tid + 1];
        g_stage.am4[tid] = make_float4(a0, a0, a1, a1);
    }
    if (tid < N_IN + 1) {
        float asum = 0.f;
        for (int r = 0; r < N_RULES; r++) asum += amask[r];
        float s = 1.0f / fmaxf(asum, 1.0f);
        float v = 0.f;
        for (int r = 0; r < N_RULES; r++)
            v += amask[r] * consequent[r * (N_IN + 1) + tid];
        v *= s;
        g_stage.vfb2[tid] = make_float2(v, v);
    }
    if (tid < N_IN) {
        g_stage.cen[tid] = make_float2(center[tid * N_MF + 0],
                                       center[tid * N_MF + 1]);
        g_stage.inv[tid] = make_float2(
            1.0f / (expf(log_sigma[tid * N_MF + 0]) + 1e-6f),
            1.0f / (expf(log_sigma[tid * N_MF + 1]) + 1e-6f));
    }
}

// ---------- main kernel: no shared memory; uniform operands via const path ----
__global__ __launch_bounds__(TPB)
void anfis_kernel(const float* __restrict__ x,   // [B,16]
                  float* __restrict__ out, int B)
{
    const int tid = threadIdx.x;
    const int rowA = blockIdx.x * (TPB * RPT) + tid;
    if (rowA >= B) return;
    int rowB = rowA + TPB;
    const bool hasB = (rowB < B);
    if (!hasB) rowB = rowA;

    // ---- load both rows (float4 vectorized, coalesced) ----
    const float4* xva = reinterpret_cast<const float4*>(x + (size_t)rowA * N_IN);
    const float4* xvb = reinterpret_cast<const float4*>(x + (size_t)rowB * N_IN);
    float4 a0 = xva[0], a1 = xva[1], a2 = xva[2], a3 = xva[3];
    float4 b0 = xvb[0], b1 = xvb[1], b2 = xvb[2], b3 = xvb[3];
    float xA[N_IN] = {a0.x, a0.y, a0.z, a0.w, a1.x, a1.y, a1.z, a1.w,
                      a2.x, a2.y, a2.z, a2.w, a3.x, a3.y, a3.z, a3.w};
    float xB[N_IN] = {b0.x, b0.y, b0.z, b0.w, b1.x, b1.y, b1.z, b1.w,
                      b2.x, b2.y, b2.z, b2.w, b3.x, b3.y, b3.z, b3.w};

    // ---- membership in log2 space; lanes = (rowA, rowB) ----
    float baseA = 0.f, baseB = 0.f;
    ull diffAB[N_IN], xAB[N_IN];
    #pragma unroll
    for (int i = 0; i < N_IN; i++) {
        float2 cen = c_blob.cen[i];
        float2 inv = c_blob.inv[i];
        float dA0 = (xA[i] - cen.x) * inv.x, dA1 = (xA[i] - cen.y) * inv.y;
        float dB0 = (xB[i] - cen.x) * inv.x, dB1 = (xB[i] - cen.y) * inv.y;
        float lA0 = dA0 * dA0 * NEG_HALF_LOG2E;
        float lA1 = dA1 * dA1 * NEG_HALF_LOG2E;
        float lB0 = dB0 * dB0 * NEG_HALF_LOG2E;
        float lB1 = dB1 * dB1 * NEG_HALF_LOG2E;
        baseA += lA0;
        baseB += lB0;
        diffAB[i] = pack2(lA1 - lA0, lB1 - lB0);
        xAB[i]    = pack2(xA[i], xB[i]);
    }
    const ull base2 = pack2(baseA, baseB);

    ull fs2  = 0ull;   // (fsA, fsB)
    ull acc2 = 0ull;   // (accA, accB)

    #pragma unroll 4
    for (int p = 0; p < NPAIR; p++) {
        // even/odd rule of the pair, rows packed in lanes
        ull tE = base2, tO = base2;
        const ulonglong2 cb =
            *reinterpret_cast<const ulonglong2*>(&c_blob.cons4[p][N_IN]);
        ull roE = cb.x, roO = cb.y;

        #pragma unroll
        for (int i = 0; i < N_IN; i++) {
            ulonglong2 m =
                *reinterpret_cast<const ulonglong2*>(&c_blob.mask4[p][i]);
            tE = ffma2(diffAB[i], m.x, tE);
            tO = ffma2(diffAB[i], m.y, tO);
            ulonglong2 c =
                *reinterpret_cast<const ulonglong2*>(&c_blob.cons4[p][i]);
            roE = ffma2(xAB[i], c.x, roE);
            roO = ffma2(xAB[i], c.y, roO);
        }

        float tEa, tEb, tOa, tOb;
        unpack2(tE, tEa, tEb);
        unpack2(tO, tOa, tOb);
        ull fE = pack2(ex2_fast(tEa), ex2_fast(tEb));
        ull fO = pack2(ex2_fast(tOa), ex2_fast(tOb));

        ulonglong2 am = *reinterpret_cast<const ulonglong2*>(&c_blob.am4[p]);
        fE = fmul2(fE, am.x);
        fO = fmul2(fO, am.y);

        fs2  = fadd2(fs2, fadd2(fE, fO));
        acc2 = ffma2(fE, roE, acc2);
        acc2 = ffma2(fO, roO, acc2);
    }

    // fallback: v_fb . x_aug (row-independent vector, 17 packed FMAs)
    ull fb2 = *reinterpret_cast<const ull*>(&c_blob.vfb2[N_IN]);  // bias
    #pragma unroll
    for (int i = 0; i < N_IN; i++)
        fb2 = ffma2(xAB[i], *reinterpret_cast<const ull*>(&c_blob.vfb2[i]), fb2);

    float fsA, fsB, accA, accB, fbA, fbB;
    unpack2(fs2, fsA, fsB);
    unpack2(acc2, accA, accB);
    unpack2(fb2, fbA, fbB);

    float zA = (fsA <= 1e-12f) ? fbA : __fdividef(accA, fsA);
    float zB = (fsB <= 1e-12f) ? fbB : __fdividef(accB, fsB);

    float sA = __fdividef(1.0f, 1.0f + ex2_fast(-zA * LOG2E));
    float sB = __fdividef(1.0f, 1.0f + ex2_fast(-zB * LOG2E));
    sA = fminf(fmaxf(sA, 1e-7f), 1.0f - 1e-7f);
    sB = fminf(fmaxf(sB, 1e-7f), 1.0f - 1e-7f);

    out[rowA] = sA;
    if (hasB) out[rowA + TPB] = sB;
}

extern "C" void kernel_launch(void* const* d_in, const int* in_sizes, int n_in,
                              void* d_out, int out_size)
{
    const float* x          = (const float*)d_in[0];
    const float* center     = (const float*)d_in[1];
    const float* log_sigma  = (const float*)d_in[2];
    const float* consequent = (const float*)d_in[3];
    const int*   rule_idx   = (const int*)  d_in[4];
    const float* amask      = (const float*)d_in[5];
    float*       out        = (float*)d_out;

    int B = in_sizes[0] / N_IN;

    // 1) build uniform-operand blob in device staging
    prep_kernel<<<1, 128>>>(center, log_sigma, consequent, rule_idx, amask);

    // 2) copy staging -> __constant__ (D2D async memcpy: graph-capturable)
    void* src = nullptr;
    cudaGetSymbolAddress(&src, g_stage);
    cudaMemcpyToSymbolAsync(c_blob, src, sizeof(Blob), 0,
                            cudaMemcpyDeviceToDevice, 0);

    // 3) main kernel
    int rows_per_block = TPB * RPT;
    int grid = (B + rows_per_block - 1) / rows_per_block;
    anfis_kernel<<<grid, TPB>>>(x, out, B);
}

// round 6
// speedup vs baseline: 1.5710x; 1.5710x over previous
#include <cuda_runtime.h>
#include <cuda_bf16.h>
#include <cstdint>

#define N_IN    16
#define N_RULES 64
#define TPB     128
#define ROWS    128
#define KDIM    96           // 6 k-tiles of 16
#define STR     104          // A/B row stride in bf16 elems (208 B)
#define STRB    208

#define OFF_A   0
#define OFF_B   26624        // 128*208
#define OFF_FB  53248        // 128 floats
#define OFF_VFB 53760        // 17 floats
#define SM_TOTAL 53888

#define NEG_HALF_LOG2E (-0.7213475204444817f)
#define LOG2E          ( 1.4426950408889634f)

// ---------------- helpers ----------------
__device__ __forceinline__ uint32_t smem_u32(const void* p) {
    uint32_t a;
    asm("{ .reg .u64 t; cvta.to.shared.u64 t, %1; cvt.u32.u64 %0, t; }"
        : "=r"(a) : "l"(p));
    return a;
}
__device__ __forceinline__ float ex2f(float v) {
    float y; asm("ex2.approx.f32 %0, %1;" : "=f"(y) : "f"(v)); return y;
}
__device__ __forceinline__ float bfh(float v) {
    return __bfloat162float(__float2bfloat16(v));
}
// pack two floats as bf16 pair: lo -> bits 0-15 (even k), hi -> bits 16-31
__device__ __forceinline__ uint32_t pkbf(float lo, float hi) {
    return (uint32_t)__bfloat16_as_ushort(__float2bfloat16(lo))
         | ((uint32_t)__bfloat16_as_ushort(__float2bfloat16(hi)) << 16);
}
__device__ __forceinline__ void ldmx4(uint32_t addr, uint32_t& r0, uint32_t& r1,
                                      uint32_t& r2, uint32_t& r3) {
    asm volatile("ldmatrix.sync.aligned.m8n8.x4.shared.b16 {%0,%1,%2,%3}, [%4];"
                 : "=r"(r0), "=r"(r1), "=r"(r2), "=r"(r3) : "r"(addr));
}
__device__ __forceinline__ void ldmx2(uint32_t addr, uint32_t& r0, uint32_t& r1) {
    asm volatile("ldmatrix.sync.aligned.m8n8.x2.shared.b16 {%0,%1}, [%2];"
                 : "=r"(r0), "=r"(r1) : "r"(addr));
}
__device__ __forceinline__ void mma16816(float& d0, float& d1, float& d2, float& d3,
                                         uint32_t a0, uint32_t a1, uint32_t a2,
                                         uint32_t a3, uint32_t b0, uint32_t b1) {
    asm volatile("mma.sync.aligned.m16n8k16.row.col.f32.bf16.bf16.f32 "
                 "{%0,%1,%2,%3}, {%4,%5,%6,%7}, {%8,%9}, {%0,%1,%2,%3};"
                 : "+f"(d0), "+f"(d1), "+f"(d2), "+f"(d3)
                 : "r"(a0), "r"(a1), "r"(a2), "r"(a3), "r"(b0), "r"(b1));
}

// K layout (96): 0-15 dh | 16-31 dm | 32-47 dl | 48=bh 49=bm 50=bl 51=0 |
//                52-67 xh | 68-83 xl | 84=1 85=1 | 86-95=0
// B row j<64 (T_j):  0-47 = bit(j, k&15); 48,49,50=1; 84=lam_h 85=lam_l; rest 0
// B row 64+r (RO_r): 52-67 = Ch; 68-83 = Ch; 84=bias_h 85=bias_l; rest 0

__global__ __launch_bounds__(TPB, 4)
void anfis_mma(const float* __restrict__ x,
               const float* __restrict__ center,
               const float* __restrict__ log_sigma,
               const float* __restrict__ consequent,
               const int*   __restrict__ rule_idx,
               const float* __restrict__ amask,
               float* __restrict__ out, int B)
{
    extern __shared__ __align__(16) char dyn[];
    __shared__ float4 s_ci[N_IN];   // (c0, c1, inv0, inv1)

    const int tid  = threadIdx.x;
    const int lane = tid & 31;
    const int warp = tid >> 5;
    const uint32_t smA = smem_u32(dyn) + OFF_A;
    const uint32_t smB = smem_u32(dyn) + OFF_B;
    float* s_fb  = reinterpret_cast<float*>(dyn + OFF_FB);
    float* s_vfb = reinterpret_cast<float*>(dyn + OFF_VFB);

    // ---- stage 0: centers / inverse sigmas ---------------------------------
    if (tid < N_IN) {
        float c0 = center[tid * 2 + 0], c1 = center[tid * 2 + 1];
        float i0 = 1.0f / (expf(log_sigma[tid * 2 + 0]) + 1e-6f);
        float i1 = 1.0f / (expf(log_sigma[tid * 2 + 1]) + 1e-6f);
        s_ci[tid] = make_float4(c0, c1, i0, i1);
    }
    __syncthreads();

    // ---- stage 1: build A row (per thread = one row) -----------------------
    const int gr = blockIdx.x * ROWS + tid;
    const int rs = (gr < B) ? gr : (B - 1);
    const float4* xv = reinterpret_cast<const float4*>(x + (size_t)rs * N_IN);
    float4 v0 = xv[0], v1 = xv[1], v2 = xv[2], v3 = xv[3];
    float xr[N_IN] = {v0.x, v0.y, v0.z, v0.w, v1.x, v1.y, v1.z, v1.w,
                      v2.x, v2.y, v2.z, v2.w, v3.x, v3.y, v3.z, v3.w};

    uint32_t w[48];
    #pragma unroll
    for (int i = 0; i < 48; i++) w[i] = 0u;

    float base = 0.f;
    #pragma unroll
    for (int i = 0; i < N_IN; i += 2) {
        float df[2], xh[2], xl[2];
        #pragma unroll
        for (int s = 0; s < 2; s++) {
            float4 ci = s_ci[i + s];
            float d0 = (xr[i + s] - ci.x) * ci.z;
            float d1 = (xr[i + s] - ci.y) * ci.w;
            float l0 = d0 * d0 * NEG_HALF_LOG2E;
            float l1 = d1 * d1 * NEG_HALF_LOG2E;
            base += l0;
            df[s] = l1 - l0;
            xh[s] = bfh(xr[i + s]);
            xl[s] = xr[i + s] - xh[s];
        }
        float h0 = bfh(df[0]), m0 = bfh(df[0] - h0);
        float h1 = bfh(df[1]), m1 = bfh(df[1] - h1);
        w[i / 2]      = pkbf(h0, h1);
        w[8 + i / 2]  = pkbf(m0, m1);
        w[16 + i / 2] = pkbf(df[0] - h0 - m0, df[1] - h1 - m1);
        w[26 + i / 2] = pkbf(xh[0], xh[1]);
        w[34 + i / 2] = pkbf(xl[0], xl[1]);
    }
    {
        float bh = bfh(base), bm = bfh(base - bh);
        w[24] = pkbf(bh, bm);
        w[25] = pkbf(base - bh - bm, 0.f);
        w[42] = pkbf(1.0f, 1.0f);
    }
    {
        uint4* dst = reinterpret_cast<uint4*>(dyn + OFF_A + tid * STRB);
        #pragma unroll
        for (int c = 0; c < 12; c++)
            dst[c] = make_uint4(w[4*c], w[4*c+1], w[4*c+2], w[4*c+3]);
    }

    // ---- stage 2: build B row (thread j = rule j or RO j-64) ---------------
    {
        uint32_t wb[48];
        #pragma unroll
        for (int i = 0; i < 48; i++) wb[i] = 0u;

        if (tid < N_RULES) {
            const int4* rv = reinterpret_cast<const int4*>(rule_idx + tid * N_IN);
            int4 b0 = rv[0], b1 = rv[1], b2 = rv[2], b3 = rv[3];
            int bits[N_IN] = {b0.x, b0.y, b0.z, b0.w, b1.x, b1.y, b1.z, b1.w,
                              b2.x, b2.y, b2.z, b2.w, b3.x, b3.y, b3.z, b3.w};
            #pragma unroll
            for (int i = 0; i < N_IN; i += 2) {
                uint32_t p = pkbf((float)bits[i], (float)bits[i + 1]);
                wb[i / 2] = p; wb[8 + i / 2] = p; wb[16 + i / 2] = p;
            }
            wb[24] = pkbf(1.0f, 1.0f);
            wb[25] = pkbf(1.0f, 0.0f);
            float am = amask[tid];
            float lam = (am > 0.f) ? log2f(am) : -60000.f;
            float lh = bfh(lam);
            wb[42] = pkbf(lh, lam - lh);
        } else {
            const int r = tid - N_RULES;
            const float* cr = consequent + r * (N_IN + 1);
            #pragma unroll
            for (int i = 0; i < N_IN; i += 2) {
                uint32_t p = pkbf(cr[i], cr[i + 1]);   // Ch pairs
                wb[26 + i / 2] = p;
                wb[34 + i / 2] = p;
            }
            float cb = cr[N_IN];
            float cbh = bfh(cb);
            wb[42] = pkbf(cbh, cb - cbh);
        }
        uint4* dst = reinterpret_cast<uint4*>(dyn + OFF_B + tid * STRB);
        #pragma unroll
        for (int c = 0; c < 12; c++)
            dst[c] = make_uint4(wb[4*c], wb[4*c+1], wb[4*c+2], wb[4*c+3]);
    }

    // ---- stage 3: fallback vector (17 threads) -----------------------------
    if (tid < N_IN + 1) {
        float den = 0.f, v = 0.f;
        for (int j = 0; j < N_RULES; j++) den += amask[j];
        den = fmaxf(den, 1.0f);
        for (int j = 0; j < N_RULES; j++)
            v += amask[j] * consequent[j * (N_IN + 1) + tid];
        s_vfb[tid] = v / den;
    }
    __syncthreads();

    // per-row fallback scalar
    {
        float fb = s_vfb[N_IN];
        #pragma unroll
        for (int i = 0; i < N_IN; i++) fb = fmaf(xr[i], s_vfb[i], fb);
        s_fb[tid] = fb;
    }
    __syncthreads();

    // ---- stage 4: MMA + in-register epilogue -------------------------------
    const int q = lane >> 2;          // quad id = row-in-8
    const int t = lane & 3;

    #pragma unroll
    for (int mt = 0; mt < 2; mt++) {
        const int R = warp * 32 + mt * 16;

        // A fragments for this 16-row slab, all 6 k-tiles (24 regs)
        uint32_t af[6][4];
        {
            int ar = R + (lane & 15);
            int ac0 = (lane >> 4) << 3;
            #pragma unroll
            for (int kt = 0; kt < 6; kt++) {
                uint32_t addr = smA + ar * STRB + (kt * 16 + ac0) * 2;
                ldmx4(addr, af[kt][0], af[kt][1], af[kt][2], af[kt][3]);
            }
        }

        float fsA = 0.f, accA = 0.f, fsB = 0.f, accB = 0.f;

        #pragma unroll
        for (int nt = 0; nt < 8; nt++) {
            float t0 = 0.f, t1 = 0.f, t2 = 0.f, t3 = 0.f;   // T tile
            float r0 = 0.f, r1 = 0.f, r2 = 0.f, r3 = 0.f;   // RO tile
            int brT = nt * 8 + (lane & 7);
            int brR = (nt + 8) * 8 + (lane & 7);
            int bc0 = lane & 8;
            #pragma unroll
            for (int kt = 0; kt < 6; kt++) {
                uint32_t b0, b1, c0, c1;
                ldmx2(smB + brT * STRB + (kt * 16 + bc0) * 2, b0, b1);
                mma16816(t0, t1, t2, t3, af[kt][0], af[kt][1], af[kt][2], af[kt][3], b0, b1);
                ldmx2(smB + brR * STRB + (kt * 16 + bc0) * 2, c0, c1);
                mma16816(r0, r1, r2, r3, af[kt][0], af[kt][1], af[kt][2], af[kt][3], c0, c1);
            }
            float f0 = ex2f(t0), f1 = ex2f(t1), f2 = ex2f(t2), f3 = ex2f(t3);
            fsA += f0 + f1;
            accA = fmaf(f0, r0, fmaf(f1, r1, accA));
            fsB += f2 + f3;
            accB = fmaf(f2, r2, fmaf(f3, r3, accB));
        }

        // reduce over the quad (cols) : xor 1, xor 2
        #pragma unroll
        for (int d = 1; d <= 2; d <<= 1) {
            fsA  += __shfl_xor_sync(0xffffffffu, fsA,  d);
            accA += __shfl_xor_sync(0xffffffffu, accA, d);
            fsB  += __shfl_xor_sync(0xffffffffu, fsB,  d);
            accB += __shfl_xor_sync(0xffffffffu, accB, d);
        }

        if (t == 0) {
            int rA = R + q, rB = R + q + 8;
            float fbA = s_fb[rA], fbB = s_fb[rB];
            float zA = (fsA <= 1e-12f) ? fbA : __fdividef(accA, fsA);
            float zB = (fsB <= 1e-12f) ? fbB : __fdividef(accB, fsB);
            float sA = __fdividef(1.0f, 1.0f + ex2f(-zA * LOG2E));
            float sB = __fdividef(1.0f, 1.0f + ex2f(-zB * LOG2E));
            sA = fminf(fmaxf(sA, 1e-7f), 1.0f - 1e-7f);
            sB = fminf(fmaxf(sB, 1e-7f), 1.0f - 1e-7f);
            int gA = blockIdx.x * ROWS + rA;
            int gB = blockIdx.x * ROWS + rB;
            if (gA < B) out[gA] = sA;
            if (gB < B) out[gB] = sB;
        }
    }
}

extern "C" void kernel_launch(void* const* d_in, const int* in_sizes, int n_in,
                              void* d_out, int out_size)
{
    const float* x          = (const float*)d_in[0];
    const float* center     = (const float*)d_in[1];
    const float* log_sigma  = (const float*)d_in[2];
    const float* consequent = (const float*)d_in[3];
    const int*   rule_idx   = (const int*)  d_in[4];
    const float* amask      = (const float*)d_in[5];
    float*       out        = (float*)d_out;

    int B = in_sizes[0] / N_IN;
    int grid = (B + ROWS - 1) / ROWS;

    cudaFuncSetAttribute(anfis_mma, cudaFuncAttributeMaxDynamicSharedMemorySize,
                         SM_TOTAL);
    anfis_mma<<<grid, TPB, SM_TOTAL>>>(x, center, log_sigma, consequent,
                                       rule_idx, amask, out, B);
}

// round 7
// speedup vs baseline: 1.8714x; 1.1912x over previous
#include <cuda_runtime.h>
#include <cuda_bf16.h>
#include <cstdint>

#define N_IN    16
#define N_RULES 64
#define TPB     128
#define ROWS    128
#define STRB    208          // A/B row stride bytes (104 bf16)

#define OFF_A   0
#define OFF_B   26624        // 128*208
#define OFF_FB  53248        // 128 floats
#define OFF_VFB 53760        // 17 floats
#define SM_TOTAL 53888

#define NEG_HALF_LOG2E (-0.7213475204444817f)
#define LOG2E          ( 1.4426950408889634f)

// ---------------- helpers ----------------
__device__ __forceinline__ uint32_t smem_u32(const void* p) {
    uint32_t a;
    asm("{ .reg .u64 t; cvta.to.shared.u64 t, %1; cvt.u32.u64 %0, t; }"
        : "=r"(a) : "l"(p));
    return a;
}
__device__ __forceinline__ float ex2f(float v) {
    float y; asm("ex2.approx.f32 %0, %1;" : "=f"(y) : "f"(v)); return y;
}
__device__ __forceinline__ float bfh(float v) {
    return __bfloat162float(__float2bfloat16(v));
}
__device__ __forceinline__ uint32_t pkbf(float lo, float hi) {
    return (uint32_t)__bfloat16_as_ushort(__float2bfloat16(lo))
         | ((uint32_t)__bfloat16_as_ushort(__float2bfloat16(hi)) << 16);
}
__device__ __forceinline__ void ldmx4(uint32_t addr, uint32_t& r0, uint32_t& r1,
                                      uint32_t& r2, uint32_t& r3) {
    asm volatile("ldmatrix.sync.aligned.m8n8.x4.shared.b16 {%0,%1,%2,%3}, [%4];"
                 : "=r"(r0), "=r"(r1), "=r"(r2), "=r"(r3) : "r"(addr));
}
__device__ __forceinline__ void ldmx2(uint32_t addr, uint32_t& r0, uint32_t& r1) {
    asm volatile("ldmatrix.sync.aligned.m8n8.x2.shared.b16 {%0,%1}, [%2];"
                 : "=r"(r0), "=r"(r1) : "r"(addr));
}
__device__ __forceinline__ void mma16816(float& d0, float& d1, float& d2, float& d3,
                                         uint32_t a0, uint32_t a1, uint32_t a2,
                                         uint32_t a3, uint32_t b0, uint32_t b1) {
    asm volatile("mma.sync.aligned.m16n8k16.row.col.f32.bf16.bf16.f32 "
                 "{%0,%1,%2,%3}, {%4,%5,%6,%7}, {%8,%9}, {%0,%1,%2,%3};"
                 : "+f"(d0), "+f"(d1), "+f"(d2), "+f"(d3)
                 : "r"(a0), "r"(a1), "r"(a2), "r"(a3), "r"(b0), "r"(b1));
}

// K layout (96), partitioned so T uses kt{0,1,2,3}, RO uses kt{3,4,5}:
//  k 0-15 dh | 16-31 dm | 32-47 dl                 (kt0-2, T only)
//  k 48=bh 49=bm 50=bl 51=1 52=1 | 53-63 xh[0..10] (kt3, shared)
//  k 64-68 xh[11..15] | 69-79 xl[0..10]            (kt4, RO only)
//  k 80-84 xl[11..15] | 85=1 86=1 | 87-95=0        (kt5, RO only)
// B T row j:  bits in 0-47 (tripled); 48,49,50=1; 51=lam_h 52=lam_l; rest 0
// B RO row r: Ch mirrored at xh and xl slots; 85=bias_h 86=bias_l; rest 0

__global__ __launch_bounds__(TPB, 4)
void anfis_mma(const float* __restrict__ x,
               const float* __restrict__ center,
               const float* __restrict__ log_sigma,
               const float* __restrict__ consequent,
               const int*   __restrict__ rule_idx,
               const float* __restrict__ amask,
               float* __restrict__ out, int B)
{
    extern __shared__ __align__(16) char dyn[];
    __shared__ float4 s_ci[N_IN];   // (c0, c1, inv0, inv1)

    const int tid  = threadIdx.x;
    const int lane = tid & 31;
    const int warp = tid >> 5;
    const uint32_t smA = smem_u32(dyn) + OFF_A;
    const uint32_t smB = smem_u32(dyn) + OFF_B;
    float* s_fb  = reinterpret_cast<float*>(dyn + OFF_FB);
    float* s_vfb = reinterpret_cast<float*>(dyn + OFF_VFB);

    // ---- stage 0 -----------------------------------------------------------
    if (tid < N_IN) {
        float c0 = center[tid * 2 + 0], c1 = center[tid * 2 + 1];
        float i0 = 1.0f / (expf(log_sigma[tid * 2 + 0]) + 1e-6f);
        float i1 = 1.0f / (expf(log_sigma[tid * 2 + 1]) + 1e-6f);
        s_ci[tid] = make_float4(c0, c1, i0, i1);
    }
    __syncthreads();

    // ---- stage 1: A row (per thread = one row) -----------------------------
    const int gr = blockIdx.x * ROWS + tid;
    const int rs = (gr < B) ? gr : (B - 1);
    const float4* xv = reinterpret_cast<const float4*>(x + (size_t)rs * N_IN);
    float4 v0 = xv[0], v1 = xv[1], v2 = xv[2], v3 = xv[3];
    float xr[N_IN] = {v0.x, v0.y, v0.z, v0.w, v1.x, v1.y, v1.z, v1.w,
                      v2.x, v2.y, v2.z, v2.w, v3.x, v3.y, v3.z, v3.w};

    {
        uint32_t w[48];
        #pragma unroll
        for (int i = 0; i < 48; i++) w[i] = 0u;

        float base = 0.f;
        float xhv[N_IN], xlv[N_IN];
        #pragma unroll
        for (int i = 0; i < N_IN; i += 2) {
            float df[2];
            #pragma unroll
            for (int s = 0; s < 2; s++) {
                float4 ci = s_ci[i + s];
                float d0 = (xr[i + s] - ci.x) * ci.z;
                float d1 = (xr[i + s] - ci.y) * ci.w;
                float l0 = d0 * d0 * NEG_HALF_LOG2E;
                float l1 = d1 * d1 * NEG_HALF_LOG2E;
                base += l0;
                df[s] = l1 - l0;
                xhv[i + s] = bfh(xr[i + s]);
                xlv[i + s] = xr[i + s] - xhv[i + s];
            }
            float h0 = bfh(df[0]), m0 = bfh(df[0] - h0);
            float h1 = bfh(df[1]), m1 = bfh(df[1] - h1);
            w[i / 2]      = pkbf(h0, h1);
            w[8 + i / 2]  = pkbf(m0, m1);
            w[16 + i / 2] = pkbf(df[0] - h0 - m0, df[1] - h1 - m1);
        }
        float bh = bfh(base), bm = bfh(base - bh);
        w[24] = pkbf(bh, bm);
        w[25] = pkbf(base - bh - bm, 1.0f);
        w[26] = pkbf(1.0f, xhv[0]);
        #pragma unroll
        for (int j = 0; j < 5; j++) w[27 + j] = pkbf(xhv[1 + 2*j], xhv[2 + 2*j]);
        w[32] = pkbf(xhv[11], xhv[12]);
        w[33] = pkbf(xhv[13], xhv[14]);
        w[34] = pkbf(xhv[15], xlv[0]);
        #pragma unroll
        for (int j = 0; j < 5; j++) w[35 + j] = pkbf(xlv[1 + 2*j], xlv[2 + 2*j]);
        w[40] = pkbf(xlv[11], xlv[12]);
        w[41] = pkbf(xlv[13], xlv[14]);
        w[42] = pkbf(xlv[15], 1.0f);
        w[43] = pkbf(1.0f, 0.0f);

        uint4* dst = reinterpret_cast<uint4*>(dyn + OFF_A + tid * STRB);
        #pragma unroll
        for (int c = 0; c < 12; c++)
            dst[c] = make_uint4(w[4*c], w[4*c+1], w[4*c+2], w[4*c+3]);
    }

    // ---- stage 2: B row ----------------------------------------------------
    {
        uint32_t wb[48];
        #pragma unroll
        for (int i = 0; i < 48; i++) wb[i] = 0u;

        if (tid < N_RULES) {
            const int4* rv = reinterpret_cast<const int4*>(rule_idx + tid * N_IN);
            int4 b0 = rv[0], b1 = rv[1], b2 = rv[2], b3 = rv[3];
            int bits[N_IN] = {b0.x, b0.y, b0.z, b0.w, b1.x, b1.y, b1.z, b1.w,
                              b2.x, b2.y, b2.z, b2.w, b3.x, b3.y, b3.z, b3.w};
            #pragma unroll
            for (int i = 0; i < N_IN; i += 2) {
                uint32_t p = pkbf((float)bits[i], (float)bits[i + 1]);
                wb[i / 2] = p; wb[8 + i / 2] = p; wb[16 + i / 2] = p;
            }
            float am = amask[tid];
            float lam = (am > 0.f) ? log2f(am) : -60000.f;
            float lh = bfh(lam);
            wb[24] = pkbf(1.0f, 1.0f);
            wb[25] = pkbf(1.0f, lh);
            wb[26] = pkbf(lam - lh, 0.0f);
        } else {
            const int r = tid - N_RULES;
            const float* cr = consequent + r * (N_IN + 1);
            float ch[N_IN];
            #pragma unroll
            for (int i = 0; i < N_IN; i++) ch[i] = cr[i];
            wb[26] = pkbf(0.0f, ch[0]);
            #pragma unroll
            for (int j = 0; j < 5; j++) wb[27 + j] = pkbf(ch[1 + 2*j], ch[2 + 2*j]);
            wb[32] = pkbf(ch[11], ch[12]);
            wb[33] = pkbf(ch[13], ch[14]);
            wb[34] = pkbf(ch[15], ch[0]);
            #pragma unroll
            for (int j = 0; j < 5; j++) wb[35 + j] = pkbf(ch[1 + 2*j], ch[2 + 2*j]);
            wb[40] = pkbf(ch[11], ch[12]);
            wb[41] = pkbf(ch[13], ch[14]);
            float cb = cr[N_IN];
            float cbh = bfh(cb);
            wb[42] = pkbf(ch[15], cbh);
            wb[43] = pkbf(cb - cbh, 0.0f);
        }
        uint4* dst = reinterpret_cast<uint4*>(dyn + OFF_B + tid * STRB);
        #pragma unroll
        for (int c = 0; c < 12; c++)
            dst[c] = make_uint4(wb[4*c], wb[4*c+1], wb[4*c+2], wb[4*c+3]);
    }

    // ---- stage 3: fallback -------------------------------------------------
    if (tid < N_IN + 1) {
        float den = 0.f, v = 0.f;
        for (int j = 0; j < N_RULES; j++) den += amask[j];
        den = fmaxf(den, 1.0f);
        for (int j = 0; j < N_RULES; j++)
            v += amask[j] * consequent[j * (N_IN + 1) + tid];
        s_vfb[tid] = v / den;
    }
    __syncthreads();
    {
        float fb = s_vfb[N_IN];
        #pragma unroll
        for (int i = 0; i < N_IN; i++) fb = fmaf(xr[i], s_vfb[i], fb);
        s_fb[tid] = fb;
    }
    __syncthreads();

    // ---- stage 4: MMA + in-register epilogue -------------------------------
    const int q = lane >> 2;
    const int t = lane & 3;

    // A fragments for both 16-row slabs, all 6 k-tiles (48 regs)
    uint32_t af[2][6][4];
    #pragma unroll
    for (int mt = 0; mt < 2; mt++) {
        int ar = warp * 32 + mt * 16 + (lane & 15);
        int ac0 = (lane >> 4) << 3;
        #pragma unroll
        for (int kt = 0; kt < 6; kt++) {
            uint32_t addr = smA + ar * STRB + (kt * 16 + ac0) * 2;
            ldmx4(addr, af[mt][kt][0], af[mt][kt][1], af[mt][kt][2], af[mt][kt][3]);
        }
    }

    float fs[2][2] = {{0.f,0.f},{0.f,0.f}};
    float acc[2][2] = {{0.f,0.f},{0.f,0.f}};

    #pragma unroll
    for (int nt = 0; nt < 8; nt++) {
        int brT = nt * 8 + (lane & 7);
        int brR = (nt + 8) * 8 + (lane & 7);
        int bc0 = lane & 8;

        // B fragments once per nt: T uses kt 0-3, RO uses kt 3-5
        uint32_t bt[4][2], br[3][2];
        #pragma unroll
        for (int k = 0; k < 4; k++)
            ldmx2(smB + brT * STRB + (k * 16 + bc0) * 2, bt[k][0], bt[k][1]);
        #pragma unroll
        for (int k = 0; k < 3; k++)
            ldmx2(smB + brR * STRB + ((k + 3) * 16 + bc0) * 2, br[k][0], br[k][1]);

        #pragma unroll
        for (int mt = 0; mt < 2; mt++) {
            float t0 = 0.f, t1 = 0.f, t2 = 0.f, t3 = 0.f;
            float r0 = 0.f, r1 = 0.f, r2 = 0.f, r3 = 0.f;
            #pragma unroll
            for (int k = 0; k < 4; k++)
                mma16816(t0, t1, t2, t3, af[mt][k][0], af[mt][k][1],
                         af[mt][k][2], af[mt][k][3], bt[k][0], bt[k][1]);
            #pragma unroll
            for (int k = 0; k < 3; k++)
                mma16816(r0, r1, r2, r3, af[mt][k+3][0], af[mt][k+3][1],
                         af[mt][k+3][2], af[mt][k+3][3], br[k][0], br[k][1]);

            float f0 = ex2f(t0), f1 = ex2f(t1), f2 = ex2f(t2), f3 = ex2f(t3);
            fs[mt][0] += f0 + f1;
            acc[mt][0] = fmaf(f0, r0, fmaf(f1, r1, acc[mt][0]));
            fs[mt][1] += f2 + f3;
            acc[mt][1] = fmaf(f2, r2, fmaf(f3, r3, acc[mt][1]));
        }
    }

    #pragma unroll
    for (int mt = 0; mt < 2; mt++) {
        float fsA = fs[mt][0], accA = acc[mt][0];
        float fsB = fs[mt][1], accB = acc[mt][1];
        #pragma unroll
        for (int d = 1; d <= 2; d <<= 1) {
            fsA  += __shfl_xor_sync(0xffffffffu, fsA,  d);
            accA += __shfl_xor_sync(0xffffffffu, accA, d);
            fsB  += __shfl_xor_sync(0xffffffffu, fsB,  d);
            accB += __shfl_xor_sync(0xffffffffu, accB, d);
        }
        if (t == 0) {
            int R = warp * 32 + mt * 16;
            int rA = R + q, rB = R + q + 8;
            float zA = (fsA <= 1e-12f) ? s_fb[rA] : __fdividef(accA, fsA);
            float zB = (fsB <= 1e-12f) ? s_fb[rB] : __fdividef(accB, fsB);
            float sA = __fdividef(1.0f, 1.0f + ex2f(-zA * LOG2E));
            float sB = __fdividef(1.0f, 1.0f + ex2f(-zB * LOG2E));
            sA = fminf(fmaxf(sA, 1e-7f), 1.0f - 1e-7f);
            sB = fminf(fmaxf(sB, 1e-7f), 1.0f - 1e-7f);
            int gA = blockIdx.x * ROWS + rA;
            int gB = blockIdx.x * ROWS + rB;
            if (gA < B) out[gA] = sA;
            if (gB < B) out[gB] = sB;
        }
    }
}

extern "C" void kernel_launch(void* const* d_in, const int* in_sizes, int n_in,
                              void* d_out, int out_size)
{
    const float* x          = (const float*)d_in[0];
    const float* center     = (const float*)d_in[1];
    const float* log_sigma  = (const float*)d_in[2];
    const float* consequent = (const float*)d_in[3];
    const int*   rule_idx   = (const int*)  d_in[4];
    const float* amask      = (const float*)d_in[5];
    float*       out        = (float*)d_out;

    int B = in_sizes[0] / N_IN;
    int grid = (B + ROWS - 1) / ROWS;

    cudaFuncSetAttribute(anfis_mma, cudaFuncAttributeMaxDynamicSharedMemorySize,
                         SM_TOTAL);
    anfis_mma<<<grid, TPB, SM_TOTAL>>>(x, center, log_sigma, consequent,
                                       rule_idx, amask, out, B);
}

// round 8
// speedup vs baseline: 1.9168x; 1.0243x over previous
#include <cuda_runtime.h>
#include <cuda_bf16.h>
#include <cstdint>

#define N_IN    16
#define N_RULES 64
#define TPB     128
#define ROWS    128

#define A_STR   176          // A row stride bytes (80 bf16 slots + pad)
#define BT_STR  112          // B-T row: 48 slots + pad
#define BR_STR  80           // B-RO row: 32 slots + pad

#define OFF_A    0
#define OFF_BT   22528       // 128*176
#define OFF_BR   (OFF_BT + 7168)
#define OFF_LAM  (OFF_BR + 5120)
#define OFF_BIAS (OFF_LAM + 256)
#define OFF_FB   (OFF_BIAS + 256)
#define OFF_BASE (OFF_FB + 512)
#define SM_TOTAL (OFF_BASE + 512)    // 36352
#define BLOB_COPY_U4 800             // 12800 B = BT+BR+LAM+BIAS

#define NEG_HALF_LOG2E (-0.7213475204444817f)
#define LOG2E          ( 1.4426950408889634f)

// ---------------- helpers ----------------
__device__ __forceinline__ uint32_t smem_u32(const void* p) {
    uint32_t a;
    asm("{ .reg .u64 t; cvta.to.shared.u64 t, %1; cvt.u32.u64 %0, t; }"
        : "=r"(a) : "l"(p));
    return a;
}
__device__ __forceinline__ float ex2f(float v) {
    float y; asm("ex2.approx.f32 %0, %1;" : "=f"(y) : "f"(v)); return y;
}
__device__ __forceinline__ float bfh(float v) {
    return __bfloat162float(__float2bfloat16(v));
}
// one-instruction pack: lo -> bits 0-15, hi -> bits 16-31
__device__ __forceinline__ uint32_t pkbf(float lo, float hi) {
    uint32_t r;
    asm("cvt.rn.bf16x2.f32 %0, %1, %2;" : "=r"(r) : "f"(hi), "f"(lo));
    return r;
}
__device__ __forceinline__ void ldmx4(uint32_t addr, uint32_t& r0, uint32_t& r1,
                                      uint32_t& r2, uint32_t& r3) {
    asm volatile("ldmatrix.sync.aligned.m8n8.x4.shared.b16 {%0,%1,%2,%3}, [%4];"
                 : "=r"(r0), "=r"(r1), "=r"(r2), "=r"(r3) : "r"(addr));
}
__device__ __forceinline__ void ldmx2(uint32_t addr, uint32_t& r0, uint32_t& r1) {
    asm volatile("ldmatrix.sync.aligned.m8n8.x2.shared.b16 {%0,%1}, [%2];"
                 : "=r"(r0), "=r"(r1) : "r"(addr));
}
__device__ __forceinline__ void mma16816(float& d0, float& d1, float& d2, float& d3,
                                         uint32_t a0, uint32_t a1, uint32_t a2,
                                         uint32_t a3, uint32_t b0, uint32_t b1) {
    asm volatile("mma.sync.aligned.m16n8k16.row.col.f32.bf16.bf16.f32 "
                 "{%0,%1,%2,%3}, {%4,%5,%6,%7}, {%8,%9}, {%0,%1,%2,%3};"
                 : "+f"(d0), "+f"(d1), "+f"(d2), "+f"(d3)
                 : "r"(a0), "r"(a1), "r"(a2), "r"(a3), "r"(b0), "r"(b1));
}

// K layout (80): kt0-2 = T (dh|dm|dl bits region), kt3 = xh[16], kt4 = xl[16]
// base(row), lam(col), bias(col) handled exactly in fp32 epilogue.
struct __align__(16) GBlob {
    uint8_t bt[64 * BT_STR];   // 7168: T rules, bits tripled across kt0-2
    uint8_t br[64 * BR_STR];   // 5120: RO rules, Ch mirrored at xh/xl slots
    float   lam[64];           // log2(amask) or -60000
    float   bias[64];          // consequent[:,16] fp32
    float4  ci[16];            // (c0, c1, inv0, inv1)
    float   vfb[20];           // fallback vector (17 used)
};
__device__ GBlob g_blob;

// ---------------- one-time prep (grid-constant data) ----------------
__global__ void prep(const float* __restrict__ center,
                     const float* __restrict__ log_sigma,
                     const float* __restrict__ consequent,
                     const int*   __restrict__ rule_idx,
                     const float* __restrict__ amask)
{
    const int tid = threadIdx.x;
    if (tid < N_RULES) {
        uint32_t* row = reinterpret_cast<uint32_t*>(g_blob.bt + tid * BT_STR);
        const int* rb = rule_idx + tid * N_IN;
        #pragma unroll
        for (int i = 0; i < N_IN; i += 2) {
            uint32_t w = pkbf((float)rb[i], (float)rb[i + 1]);
            row[i / 2] = w; row[8 + i / 2] = w; row[16 + i / 2] = w;
        }
        row[24] = row[25] = row[26] = row[27] = 0;
        float am = amask[tid];
        g_blob.lam[tid]  = (am > 0.f) ? log2f(am) : -60000.f;
        g_blob.bias[tid] = consequent[tid * 17 + 16];
    } else {
        const int r = tid - N_RULES;
        uint32_t* row = reinterpret_cast<uint32_t*>(g_blob.br + r * BR_STR);
        const float* cr = consequent + r * 17;
        #pragma unroll
        for (int i = 0; i < N_IN; i += 2) {
            uint32_t w = pkbf(cr[i], cr[i + 1]);
            row[i / 2] = w; row[8 + i / 2] = w;
        }
        row[16] = row[17] = row[18] = row[19] = 0;
    }
    if (tid < N_IN) {
        g_blob.ci[tid] = make_float4(
            center[tid * 2 + 0], center[tid * 2 + 1],
            1.0f / (expf(log_sigma[tid * 2 + 0]) + 1e-6f),
            1.0f / (expf(log_sigma[tid * 2 + 1]) + 1e-6f));
    }
    if (tid < N_IN + 1) {
        float den = 0.f, v = 0.f;
        for (int j = 0; j < N_RULES; j++) den += amask[j];
        den = fmaxf(den, 1.0f);
        for (int j = 0; j < N_RULES; j++)
            v += amask[j] * consequent[j * 17 + tid];
        g_blob.vfb[tid] = v / den;
    }
}

// ---------------- main kernel ----------------
__global__ __launch_bounds__(TPB, 5)
void anfis_mma(const float* __restrict__ x, float* __restrict__ out, int B)
{
    extern __shared__ __align__(16) char dyn[];
    const int tid  = threadIdx.x;
    const int lane = tid & 31;
    const int warp = tid >> 5;
    const uint32_t smA = smem_u32(dyn);

    // ---- copy grid-constant blob into smem (BT|BR|LAM|BIAS contiguous) ----
    {
        const uint4* src = reinterpret_cast<const uint4*>(&g_blob);
        uint4* dst = reinterpret_cast<uint4*>(dyn + OFF_BT);
        #pragma unroll
        for (int i = tid; i < BLOB_COPY_U4; i += TPB) dst[i] = src[i];
    }

    // ---- build A row (per thread = one row) + base + fallback -------------
    const int gr = blockIdx.x * ROWS + tid;
    const int rs = (gr < B) ? gr : (B - 1);
    const float4* xv = reinterpret_cast<const float4*>(x + (size_t)rs * N_IN);
    float4 v0 = xv[0], v1 = xv[1], v2 = xv[2], v3 = xv[3];
    float xr[N_IN] = {v0.x, v0.y, v0.z, v0.w, v1.x, v1.y, v1.z, v1.w,
                      v2.x, v2.y, v2.z, v2.w, v3.x, v3.y, v3.z, v3.w};

    float base = 0.f;
    float fb = __ldg(&g_blob.vfb[N_IN]);
    uint32_t wdh[8], wdm[8], wdl[8], wxh[8], wxl[8];
    #pragma unroll
    for (int i = 0; i < N_IN; i += 2) {
        float df[2], xh[2], xl[2];
        #pragma unroll
        for (int s = 0; s < 2; s++) {
            float4 ci = __ldg(&g_blob.ci[i + s]);
            float d0 = (xr[i + s] - ci.x) * ci.z;
            float d1 = (xr[i + s] - ci.y) * ci.w;
            float l0 = d0 * d0 * NEG_HALF_LOG2E;
            float l1 = d1 * d1 * NEG_HALF_LOG2E;
            base += l0;
            df[s] = l1 - l0;
            xh[s] = bfh(xr[i + s]);
            xl[s] = xr[i + s] - xh[s];
            fb = fmaf(xr[i + s], __ldg(&g_blob.vfb[i + s]), fb);
        }
        float h0 = bfh(df[0]), m0 = bfh(df[0] - h0);
        float h1 = bfh(df[1]), m1 = bfh(df[1] - h1);
        wdh[i / 2] = pkbf(h0, h1);
        wdm[i / 2] = pkbf(m0, m1);
        wdl[i / 2] = pkbf(df[0] - h0 - m0, df[1] - h1 - m1);
        wxh[i / 2] = pkbf(xh[0], xh[1]);
        wxl[i / 2] = pkbf(xl[0], xl[1]);
    }
    {
        uint4* arow = reinterpret_cast<uint4*>(dyn + OFF_A + tid * A_STR);
        arow[0] = make_uint4(wdh[0], wdh[1], wdh[2], wdh[3]);
        arow[1] = make_uint4(wdh[4], wdh[5], wdh[6], wdh[7]);
        arow[2] = make_uint4(wdm[0], wdm[1], wdm[2], wdm[3]);
        arow[3] = make_uint4(wdm[4], wdm[5], wdm[6], wdm[7]);
        arow[4] = make_uint4(wdl[0], wdl[1], wdl[2], wdl[3]);
        arow[5] = make_uint4(wdl[4], wdl[5], wdl[6], wdl[7]);
        arow[6] = make_uint4(wxh[0], wxh[1], wxh[2], wxh[3]);
        arow[7] = make_uint4(wxh[4], wxh[5], wxh[6], wxh[7]);
        arow[8] = make_uint4(wxl[0], wxl[1], wxl[2], wxl[3]);
        arow[9] = make_uint4(wxl[4], wxl[5], wxl[6], wxl[7]);
        reinterpret_cast<float*>(dyn + OFF_BASE)[tid] = base;
        reinterpret_cast<float*>(dyn + OFF_FB)[tid]   = fb;
    }
    __syncthreads();

    // ---- MMA + fp32 epilogue ----------------------------------------------
    const int q = lane >> 2;
    const int t = lane & 3;
    const uint32_t smBT = smA + OFF_BT;
    const uint32_t smBR = smA + OFF_BR;
    const float* sBase = reinterpret_cast<const float*>(dyn + OFF_BASE);
    const float* sFb   = reinterpret_cast<const float*>(dyn + OFF_FB);
    const float2* lam2  = reinterpret_cast<const float2*>(dyn + OFF_LAM);
    const float2* bias2 = reinterpret_cast<const float2*>(dyn + OFF_BIAS);

    uint32_t af[2][5][4];
    float baseR[2][2];
    #pragma unroll
    for (int mt = 0; mt < 2; mt++) {
        int R = warp * 32 + mt * 16;
        int ar = R + (lane & 15);
        int ac0 = (lane >> 4) << 3;
        #pragma unroll
        for (int kt = 0; kt < 5; kt++)
            ldmx4(smA + ar * A_STR + (kt * 16 + ac0) * 2,
                  af[mt][kt][0], af[mt][kt][1], af[mt][kt][2], af[mt][kt][3]);
        baseR[mt][0] = sBase[R + q];
        baseR[mt][1] = sBase[R + q + 8];
    }

    float fs[2][2]  = {{0.f, 0.f}, {0.f, 0.f}};
    float acc[2][2] = {{0.f, 0.f}, {0.f, 0.f}};

    #pragma unroll
    for (int nt = 0; nt < 8; nt++) {
        int brj = nt * 8 + (lane & 7);
        int bc0 = lane & 8;
        uint32_t bt[3][2], br[2][2];
        #pragma unroll
        for (int k = 0; k < 3; k++)
            ldmx2(smBT + brj * BT_STR + (k * 16 + bc0) * 2, bt[k][0], bt[k][1]);
        #pragma unroll
        for (int k = 0; k < 2; k++)
            ldmx2(smBR + brj * BR_STR + (k * 16 + bc0) * 2, br[k][0], br[k][1]);

        float2 lm = lam2[nt * 4 + t];
        float2 bs = bias2[nt * 4 + t];

        #pragma unroll
        for (int mt = 0; mt < 2; mt++) {
            float t0 = 0.f, t1 = 0.f, t2 = 0.f, t3 = 0.f;
            float r0 = 0.f, r1 = 0.f, r2 = 0.f, r3 = 0.f;
            #pragma unroll
            for (int k = 0; k < 3; k++)
                mma16816(t0, t1, t2, t3, af[mt][k][0], af[mt][k][1],
                         af[mt][k][2], af[mt][k][3], bt[k][0], bt[k][1]);
            #pragma unroll
            for (int k = 0; k < 2; k++)
                mma16816(r0, r1, r2, r3, af[mt][k + 3][0], af[mt][k + 3][1],
                         af[mt][k + 3][2], af[mt][k + 3][3], br[k][0], br[k][1]);

            float f0 = ex2f(t0 + baseR[mt][0] + lm.x);
            float f1 = ex2f(t1 + baseR[mt][0] + lm.y);
            float f2 = ex2f(t2 + baseR[mt][1] + lm.x);
            float f3 = ex2f(t3 + baseR[mt][1] + lm.y);
            fs[mt][0] += f0 + f1;
            acc[mt][0] = fmaf(f0, r0 + bs.x, fmaf(f1, r1 + bs.y, acc[mt][0]));
            fs[mt][1] += f2 + f3;
            acc[mt][1] = fmaf(f2, r2 + bs.x, fmaf(f3, r3 + bs.y, acc[mt][1]));
        }
    }

    #pragma unroll
    for (int mt = 0; mt < 2; mt++) {
        float fsA = fs[mt][0], accA = acc[mt][0];
        float fsB = fs[mt][1], accB = acc[mt][1];
        #pragma unroll
        for (int d = 1; d <= 2; d <<= 1) {
            fsA  += __shfl_xor_sync(0xffffffffu, fsA,  d);
            accA += __shfl_xor_sync(0xffffffffu, accA, d);
            fsB  += __shfl_xor_sync(0xffffffffu, fsB,  d);
            accB += __shfl_xor_sync(0xffffffffu, accB, d);
        }
        if (t == 0) {
            int R = warp * 32 + mt * 16;
            int rA = R + q, rB = R + q + 8;
            float zA = (fsA <= 1e-12f) ? sFb[rA] : __fdividef(accA, fsA);
            float zB = (fsB <= 1e-12f) ? sFb[rB] : __fdividef(accB, fsB);
            float sA = __fdividef(1.0f, 1.0f + ex2f(-zA * LOG2E));
            float sB = __fdividef(1.0f, 1.0f + ex2f(-zB * LOG2E));
            sA = fminf(fmaxf(sA, 1e-7f), 1.0f - 1e-7f);
            sB = fminf(fmaxf(sB, 1e-7f), 1.0f - 1e-7f);
            int gA = blockIdx.x * ROWS + rA;
            int gB = blockIdx.x * ROWS + rB;
            if (gA < B) out[gA] = sA;
            if (gB < B) out[gB] = sB;
        }
    }
}

extern "C" void kernel_launch(void* const* d_in, const int* in_sizes, int n_in,
                              void* d_out, int out_size)
{
    const float* x          = (const float*)d_in[0];
    const float* center     = (const float*)d_in[1];
    const float* log_sigma  = (const float*)d_in[2];
    const float* consequent = (const float*)d_in[3];
    const int*   rule_idx   = (const int*)  d_in[4];
    const float* amask      = (const float*)d_in[5];
    float*       out        = (float*)d_out;

    int B = in_sizes[0] / N_IN;
    int grid = (B + ROWS - 1) / ROWS;

    prep<<<1, TPB>>>(center, log_sigma, consequent, rule_idx, amask);

    cudaFuncSetAttribute(anfis_mma, cudaFuncAttributeMaxDynamicSharedMemorySize,
                         SM_TOTAL);
    anfis_mma<<<grid, TPB, SM_TOTAL>>>(x, out, B);
}

// round 11
// speedup vs baseline: 2.1559x; 1.1248x over previous
#include <cuda_runtime.h>
#include <cuda_bf16.h>
#include <cstdint>

#define N_IN    16
#define N_RULES 64
#define TPB     128
#define ROWS    128

#define A_STR   176          // A row stride bytes (80 bf16 slots + pad)
#define BT_STR  112          // B-T row: 48 slots + pad
#define BR_STR  80           // B-RO row: 32 slots + pad

#define OFF_A    0
#define OFF_BT   22528       // 128*176
#define OFF_BR   (OFF_BT + 7168)
#define OFF_LAM  (OFF_BR + 5120)
#define OFF_BIAS (OFF_LAM + 256)
#define OFF_AM   (OFF_BIAS + 256)
#define OFF_BASE (OFF_AM + 256)
#define SM_TOTAL (OFF_BASE + 512)    // 36352

#define NEG_HALF_LOG2E (-0.7213475204444817f)
#define LOG2E          ( 1.4426950408889634f)

// ---------------- helpers ----------------
__device__ __forceinline__ uint32_t smem_u32(const void* p) {
    uint32_t a;
    asm("{ .reg .u64 t; cvta.to.shared.u64 t, %1; cvt.u32.u64 %0, t; }"
        : "=r"(a) : "l"(p));
    return a;
}
__device__ __forceinline__ float ex2f(float v) {
    float y; asm("ex2.approx.f32 %0, %1;" : "=f"(y) : "f"(v)); return y;
}
__device__ __forceinline__ float lg2f(float v) {
    float y; asm("lg2.approx.f32 %0, %1;" : "=f"(y) : "f"(v)); return y;
}
__device__ __forceinline__ float bfh(float v) {
    return __bfloat162float(__float2bfloat16(v));
}
// one-instruction pack: lo -> bits 0-15, hi -> bits 16-31
__device__ __forceinline__ uint32_t pkbf(float lo, float hi) {
    uint32_t r;
    asm("cvt.rn.bf16x2.f32 %0, %1, %2;" : "=r"(r) : "f"(hi), "f"(lo));
    return r;
}
__device__ __forceinline__ void ldmx4(uint32_t addr, uint32_t& r0, uint32_t& r1,
                                      uint32_t& r2, uint32_t& r3) {
    asm volatile("ldmatrix.sync.aligned.m8n8.x4.shared.b16 {%0,%1,%2,%3}, [%4];"
                 : "=r"(r0), "=r"(r1), "=r"(r2), "=r"(r3) : "r"(addr));
}
__device__ __forceinline__ void ldmx2(uint32_t addr, uint32_t& r0, uint32_t& r1) {
    asm volatile("ldmatrix.sync.aligned.m8n8.x2.shared.b16 {%0,%1}, [%2];"
                 : "=r"(r0), "=r"(r1) : "r"(addr));
}
__device__ __forceinline__ void mma16816(float& d0, float& d1, float& d2, float& d3,
                                         uint32_t a0, uint32_t a1, uint32_t a2,
                                         uint32_t a3, uint32_t b0, uint32_t b1) {
    asm volatile("mma.sync.aligned.m16n8k16.row.col.f32.bf16.bf16.f32 "
                 "{%0,%1,%2,%3}, {%4,%5,%6,%7}, {%8,%9}, {%0,%1,%2,%3};"
                 : "+f"(d0), "+f"(d1), "+f"(d2), "+f"(d3)
                 : "r"(a0), "r"(a1), "r"(a2), "r"(a3), "r"(b0), "r"(b1));
}

// K layout (80): kt0-2 = T (dh|dm|dl x bits), kt3 = xh[16], kt4 = xl[16]
// base(row), lam(col), bias(col) applied exactly in the fp32 epilogue.
// Fallback = (sum_j am_j * ro_j) / max(sum am, 1) — accumulated in-loop.

__global__ __launch_bounds__(TPB, 5)
void anfis_mma(const float* __restrict__ x,
               const float* __restrict__ center,
               const float* __restrict__ log_sigma,
               const float* __restrict__ consequent,
               const int*   __restrict__ rule_idx,
               const float* __restrict__ amask,
               float* __restrict__ out, int B)
{
    extern __shared__ __align__(16) char dyn[];
    __shared__ float4 s_ci[N_IN];   // (c0, c1, inv0, inv1)

    const int tid  = threadIdx.x;
    const int lane = tid & 31;
    const int warp = tid >> 5;
    const uint32_t smA = smem_u32(dyn);

    // ---- stage 0: centers / inverse sigmas ---------------------------------
    if (tid < N_IN) {
        float c0 = center[tid * 2 + 0], c1 = center[tid * 2 + 1];
        float i0 = 1.0f / (ex2f(log_sigma[tid * 2 + 0] * LOG2E) + 1e-6f);
        float i1 = 1.0f / (ex2f(log_sigma[tid * 2 + 1] * LOG2E) + 1e-6f);
        s_ci[tid] = make_float4(c0, c1, i0, i1);
    }
    __syncthreads();

    // ---- stage 1: A row (per thread = one row) + base ----------------------
    const int gr = blockIdx.x * ROWS + tid;
    const int rs = (gr < B) ? gr : (B - 1);
    const float4* xv = reinterpret_cast<const float4*>(x + (size_t)rs * N_IN);
    float4 v0 = xv[0], v1 = xv[1], v2 = xv[2], v3 = xv[3];
    float xr[N_IN] = {v0.x, v0.y, v0.z, v0.w, v1.x, v1.y, v1.z, v1.w,
                      v2.x, v2.y, v2.z, v2.w, v3.x, v3.y, v3.z, v3.w};

    float base = 0.f;
    uint32_t wdh[8], wdm[8], wdl[8], wxh[8], wxl[8];
    #pragma unroll
    for (int i = 0; i < N_IN; i += 2) {
        float df[2], xh[2], xl[2];
        #pragma unroll
        for (int s = 0; s < 2; s++) {
            float4 ci = s_ci[i + s];
            float d0 = (xr[i + s] - ci.x) * ci.z;
            float d1 = (xr[i + s] - ci.y) * ci.w;
            float l0 = d0 * d0 * NEG_HALF_LOG2E;
            float l1 = d1 * d1 * NEG_HALF_LOG2E;
            base += l0;
            df[s] = l1 - l0;
            xh[s] = bfh(xr[i + s]);
            xl[s] = xr[i + s] - xh[s];
        }
        float h0 = bfh(df[0]), m0 = bfh(df[0] - h0);
        float h1 = bfh(df[1]), m1 = bfh(df[1] - h1);
        wdh[i / 2] = pkbf(h0, h1);
        wdm[i / 2] = pkbf(m0, m1);
        wdl[i / 2] = pkbf(df[0] - h0 - m0, df[1] - h1 - m1);
        wxh[i / 2] = pkbf(xh[0], xh[1]);
        wxl[i / 2] = pkbf(xl[0], xl[1]);
    }
    {
        uint4* arow = reinterpret_cast<uint4*>(dyn + OFF_A + tid * A_STR);
        arow[0] = make_uint4(wdh[0], wdh[1], wdh[2], wdh[3]);
        arow[1] = make_uint4(wdh[4], wdh[5], wdh[6], wdh[7]);
        arow[2] = make_uint4(wdm[0], wdm[1], wdm[2], wdm[3]);
        arow[3] = make_uint4(wdm[4], wdm[5], wdm[6], wdm[7]);
        arow[4] = make_uint4(wdl[0], wdl[1], wdl[2], wdl[3]);
        arow[5] = make_uint4(wdl[4], wdl[5], wdl[6], wdl[7]);
        arow[6] = make_uint4(wxh[0], wxh[1], wxh[2], wxh[3]);
        arow[7] = make_uint4(wxh[4], wxh[5], wxh[6], wxh[7]);
        arow[8] = make_uint4(wxl[0], wxl[1], wxl[2], wxl[3]);
        arow[9] = make_uint4(wxl[4], wxl[5], wxl[6], wxl[7]);
        reinterpret_cast<float*>(dyn + OFF_BASE)[tid] = base;
    }

    // ---- stage 2: B rows in-CTA (thread j = rule j or RO j-64) -------------
    if (tid < N_RULES) {
        const int4* rv = reinterpret_cast<const int4*>(rule_idx + tid * N_IN);
        int4 b0 = rv[0], b1 = rv[1], b2 = rv[2], b3 = rv[3];
        int bits[N_IN] = {b0.x, b0.y, b0.z, b0.w, b1.x, b1.y, b1.z, b1.w,
                          b2.x, b2.y, b2.z, b2.w, b3.x, b3.y, b3.z, b3.w};
        uint32_t wb[8];
        #pragma unroll
        for (int i = 0; i < N_IN; i += 2)
            wb[i / 2] = pkbf((float)bits[i], (float)bits[i + 1]);
        uint4* row = reinterpret_cast<uint4*>(dyn + OFF_BT + tid * BT_STR);
        uint4 lo = make_uint4(wb[0], wb[1], wb[2], wb[3]);
        uint4 hi = make_uint4(wb[4], wb[5], wb[6], wb[7]);
        row[0] = lo; row[1] = hi;
        row[2] = lo; row[3] = hi;
        row[4] = lo; row[5] = hi;
        row[6] = make_uint4(0, 0, 0, 0);
        float am = amask[tid];
        reinterpret_cast<float*>(dyn + OFF_LAM)[tid]  = lg2f(am); // am=0 -> -inf -> firing 0
        reinterpret_cast<float*>(dyn + OFF_BIAS)[tid] = consequent[tid * 17 + 16];
        reinterpret_cast<float*>(dyn + OFF_AM)[tid]   = am;
    } else {
        const int r = tid - N_RULES;
        const float* cr = consequent + r * 17;
        uint32_t wb[8];
        #pragma unroll
        for (int i = 0; i < N_IN; i += 2)
            wb[i / 2] = pkbf(cr[i], cr[i + 1]);
        uint4* row = reinterpret_cast<uint4*>(dyn + OFF_BR + r * BR_STR);
        uint4 lo = make_uint4(wb[0], wb[1], wb[2], wb[3]);
        uint4 hi = make_uint4(wb[4], wb[5], wb[6], wb[7]);
        row[0] = lo; row[1] = hi;   // xh slots
        row[2] = lo; row[3] = hi;   // xl slots (same Ch)
        row[4] = make_uint4(0, 0, 0, 0);
    }
    __syncthreads();

    // ---- stage 3: MMA + fp32 epilogue (fallback fused) ---------------------
    const int q = lane >> 2;
    const int t = lane & 3;
    const uint32_t smBT = smA + OFF_BT;
    const uint32_t smBR = smA + OFF_BR;
    const float* sBase  = reinterpret_cast<const float*>(dyn + OFF_BASE);
    const float2* lam2  = reinterpret_cast<const float2*>(dyn + OFF_LAM);
    const float2* bias2 = reinterpret_cast<const float2*>(dyn + OFF_BIAS);
    const float2* am2   = reinterpret_cast<const float2*>(dyn + OFF_AM);

    uint32_t af[2][5][4];
    float baseR[2][2];
    #pragma unroll
    for (int mt = 0; mt < 2; mt++) {
        int R = warp * 32 + mt * 16;
        int ar = R + (lane & 15);
        int ac0 = (lane >> 4) << 3;
        #pragma unroll
        for (int kt = 0; kt < 5; kt++)
            ldmx4(smA + ar * A_STR + (kt * 16 + ac0) * 2,
                  af[mt][kt][0], af[mt][kt][1], af[mt][kt][2], af[mt][kt][3]);
        baseR[mt][0] = sBase[R + q];
        baseR[mt][1] = sBase[R + q + 8];
    }

    float fs[2][2]  = {{0.f, 0.f}, {0.f, 0.f}};
    float acc[2][2] = {{0.f, 0.f}, {0.f, 0.f}};
    float fba[2][2] = {{0.f, 0.f}, {0.f, 0.f}};
    float dsum = 0.f;

    #pragma unroll
    for (int nt = 0; nt < 8; nt++) {
        int brj = nt * 8 + (lane & 7);
        int bc0 = lane & 8;
        uint32_t bt[3][2], br[2][2];
        #pragma unroll
        for (int k = 0; k < 3; k++)
            ldmx2(smBT + brj * BT_STR + (k * 16 + bc0) * 2, bt[k][0], bt[k][1]);
        #pragma unroll
        for (int k = 0; k < 2; k++)
            ldmx2(smBR + brj * BR_STR + (k * 16 + bc0) * 2, br[k][0], br[k][1]);

        float2 lm = lam2[nt * 4 + t];
        float2 bs = bias2[nt * 4 + t];
        float2 av = am2[nt * 4 + t];
        dsum += av.x + av.y;

        #pragma unroll
        for (int mt = 0; mt < 2; mt++) {
            float t0 = 0.f, t1 = 0.f, t2 = 0.f, t3 = 0.f;
            float r0 = 0.f, r1 = 0.f, r2 = 0.f, r3 = 0.f;
            #pragma unroll
            for (int k = 0; k < 3; k++)
                mma16816(t0, t1, t2, t3, af[mt][k][0], af[mt][k][1],
                         af[mt][k][2], af[mt][k][3], bt[k][0], bt[k][1]);
            #pragma unroll
            for (int k = 0; k < 2; k++)
                mma16816(r0, r1, r2, r3, af[mt][k + 3][0], af[mt][k + 3][1],
                         af[mt][k + 3][2], af[mt][k + 3][3], br[k][0], br[k][1]);

            float ro0 = r0 + bs.x, ro1 = r1 + bs.y;
            float ro2 = r2 + bs.x, ro3 = r3 + bs.y;
            float f0 = ex2f(t0 + baseR[mt][0] + lm.x);
            float f1 = ex2f(t1 + baseR[mt][0] + lm.y);
            float f2 = ex2f(t2 + baseR[mt][1] + lm.x);
            float f3 = ex2f(t3 + baseR[mt][1] + lm.y);
            fs[mt][0] += f0 + f1;
            acc[mt][0] = fmaf(f0, ro0, fmaf(f1, ro1, acc[mt][0]));
            fba[mt][0] = fmaf(av.x, ro0, fmaf(av.y, ro1, fba[mt][0]));
            fs[mt][1] += f2 + f3;
            acc[mt][1] = fmaf(f2, ro2, fmaf(f3, ro3, acc[mt][1]));
            fba[mt][1] = fmaf(av.x, ro2, fmaf(av.y, ro3, fba[mt][1]));
        }
    }

    #pragma unroll
    for (int d = 1; d <= 2; d <<= 1)
        dsum += __shfl_xor_sync(0xffffffffu, dsum, d);
    const float inv_den = __fdividef(1.0f, fmaxf(dsum, 1.0f));

    #pragma unroll
    for (int mt = 0; mt < 2; mt++) {
        float fsA = fs[mt][0], accA = acc[mt][0], fbA = fba[mt][0];
        float fsB = fs[mt][1], accB = acc[mt][1], fbB = fba[mt][1];
        #pragma unroll
        for (int d = 1; d <= 2; d <<= 1) {
            fsA  += __shfl_xor_sync(0xffffffffu, fsA,  d);
            accA += __shfl_xor_sync(0xffffffffu, accA, d);
            fbA  += __shfl_xor_sync(0xffffffffu, fbA,  d);
            fsB  += __shfl_xor_sync(0xffffffffu, fsB,  d);
            accB += __shfl_xor_sync(0xffffffffu, accB, d);
            fbB  += __shfl_xor_sync(0xffffffffu, fbB,  d);
        }
        if (t == 0) {
            int R = warp * 32 + mt * 16;
            int rA = R + q, rB = R + q + 8;
            float zA = (fsA <= 1e-12f) ? (fbA * inv_den) : __fdividef(accA, fsA);
            float zB = (fsB <= 1e-12f) ? (fbB * inv_den) : __fdividef(accB, fsB);
            float sA = __fdividef(1.0f, 1.0f + ex2f(-zA * LOG2E));
            float sB = __fdividef(1.0f, 1.0f + ex2f(-zB * LOG2E));
            sA = fminf(fmaxf(sA, 1e-7f), 1.0f - 1e-7f);
            sB = fminf(fmaxf(sB, 1e-7f), 1.0f - 1e-7f);
            int gA = blockIdx.x * ROWS + rA;
            int gB = blockIdx.x * ROWS + rB;
            if (gA < B) out[gA] = sA;
            if (gB < B) out[gB] = sB;
        }
    }
}

extern "C" void kernel_launch(void* const* d_in, const int* in_sizes, int n_in,
                              void* d_out, int out_size)
{
    const float* x          = (const float*)d_in[0];
    const float* center     = (const float*)d_in[1];
    const float* log_sigma  = (const float*)d_in[2];
    const float* consequent = (const float*)d_in[3];
    const int*   rule_idx   = (const int*)  d_in[4];
    const float* amask      = (const float*)d_in[5];
    float*       out        = (float*)d_out;

    int B = in_sizes[0] / N_IN;
    int grid = (B + ROWS - 1) / ROWS;

    cudaFuncSetAttribute(anfis_mma, cudaFuncAttributeMaxDynamicSharedMemorySize,
                         SM_TOTAL);
    anfis_mma<<<grid, TPB, SM_TOTAL>>>(x, center, log_sigma, consequent,
                                       rule_idx, amask, out, B);
}